// round 4
// baseline (speedup 1.0000x reference)
#include <cuda_runtime.h>
#include <math.h>

#define NPTS 4096
#define NB   8
#define KNN  10
#define TPB  256

// scratch normals: [cloud][component][b*NPTS + n]
__device__ float g_nrm[2][3][NB * NPTS];

__device__ __forceinline__ void try_insert(float (&dist)[KNN], int (&idx)[KNN],
                                           float dd, int jj) {
    if (dd < dist[KNN - 1]) {
#pragma unroll
        for (int r = 0; r < KNN; ++r) {
            if (dd < dist[r]) {
                float td = dist[r]; int ti = idx[r];
                dist[r] = dd; idx[r] = jj;
                dd = td; jj = ti;
            }
        }
    }
}

__global__ void __launch_bounds__(TPB, 2)
normals_kernel(const float* __restrict__ pred, const float* __restrict__ gt) {
    extern __shared__ float4 s[];   // 4096 x (x, y, z, |c|^2) = 64 KB

    const int cloud = blockIdx.z;
    const int b     = blockIdx.y;
    const float* __restrict__ base =
        ((cloud == 0) ? pred : gt) + (size_t)b * 3 * NPTS;

    // cooperative load of the whole cloud-batch into shared
    for (int t = threadIdx.x; t < NPTS; t += TPB) {
        float x = base[t];
        float y = base[NPTS + t];
        float z = base[2 * NPTS + t];
        s[t] = make_float4(x, y, z, fmaf(x, x, fmaf(y, y, z * z)));
    }
    __syncthreads();

    const int p = blockIdx.x * TPB + threadIdx.x;   // query point
    const float4 q = s[p];
    const float ax = -2.0f * q.x, ay = -2.0f * q.y, az = -2.0f * q.z;

    // register-resident sorted top-10 (ascending distance proxy)
    float dist[KNN]; int idx[KNN];
#pragma unroll
    for (int r = 0; r < KNN; ++r) { dist[r] = 3.4e38f; idx[r] = 0; }

    // distance proxy: |c|^2 - 2 q.c  (order-identical to true d2; |q|^2 const)
    for (int j = 0; j < NPTS; j += 4) {
        float4 c0 = s[j + 0];
        float4 c1 = s[j + 1];
        float4 c2 = s[j + 2];
        float4 c3 = s[j + 3];
        float d0 = fmaf(ax, c0.x, fmaf(ay, c0.y, fmaf(az, c0.z, c0.w)));
        float d1 = fmaf(ax, c1.x, fmaf(ay, c1.y, fmaf(az, c1.z, c1.w)));
        float d2 = fmaf(ax, c2.x, fmaf(ay, c2.y, fmaf(az, c2.z, c2.w)));
        float d3 = fmaf(ax, c3.x, fmaf(ay, c3.y, fmaf(az, c3.z, c3.w)));
        float m = fminf(fminf(d0, d1), fminf(d2, d3));
        if (m < dist[KNN - 1]) {          // rare path (~60 hits / 1024 iters)
            try_insert(dist, idx, d0, j + 0);
            try_insert(dist, idx, d1, j + 1);
            try_insert(dist, idx, d2, j + 2);
            try_insert(dist, idx, d3, j + 3);
        }
    }

    // ---- local covariance of the 10 neighbors (centered on q for stability) --
    float mx = 0.f, my = 0.f, mz = 0.f;
#pragma unroll
    for (int r = 0; r < KNN; ++r) {
        float4 c = s[idx[r]];
        mx += c.x - q.x; my += c.y - q.y; mz += c.z - q.z;
    }
    const float invk = 1.0f / (float)KNN;
    mx *= invk; my *= invk; mz *= invk;

    float cxx = 0.f, cxy = 0.f, cxz = 0.f, cyy = 0.f, cyz = 0.f, czz = 0.f;
#pragma unroll
    for (int r = 0; r < KNN; ++r) {
        float4 c = s[idx[r]];
        float dx = (c.x - q.x) - mx;
        float dy = (c.y - q.y) - my;
        float dz = (c.z - q.z) - mz;
        cxx = fmaf(dx, dx, cxx); cxy = fmaf(dx, dy, cxy); cxz = fmaf(dx, dz, cxz);
        cyy = fmaf(dy, dy, cyy); cyz = fmaf(dy, dz, cyz); czz = fmaf(dz, dz, czz);
    }

    // ---- analytic smallest-eigenvector of 3x3 symmetric (double precision) ---
    double a00 = (double)cxx * invk, a01 = (double)cxy * invk, a02 = (double)cxz * invk;
    double a11 = (double)cyy * invk, a12 = (double)cyz * invk, a22 = (double)czz * invk;

    double vx = 1.0, vy = 0.0, vz = 0.0;

    double tr3 = (a00 + a11 + a22) * (1.0 / 3.0);
    double b00 = a00 - tr3, b11 = a11 - tr3, b22 = a22 - tr3;
    double p2 = b00 * b00 + b11 * b11 + b22 * b22
              + 2.0 * (a01 * a01 + a02 * a02 + a12 * a12);
    if (p2 > 0.0) {
        double pp = sqrt(p2 * (1.0 / 6.0));
        double ip = 1.0 / pp;
        double db00 = b00 * ip, db11 = b11 * ip, db22 = b22 * ip;
        double da01 = a01 * ip, da02 = a02 * ip, da12 = a12 * ip;
        double halfdet = 0.5 * (db00 * (db11 * db22 - da12 * da12)
                              - da01 * (da01 * db22 - da12 * da02)
                              + da02 * (da01 * da12 - db11 * da02));
        halfdet = fmin(fmax(halfdet, -1.0), 1.0);
        double ang  = acos(halfdet) * (1.0 / 3.0);
        double lmin = tr3 + 2.0 * pp * cos(ang + 2.0943951023931953);  // +2pi/3

        double m00 = a00 - lmin, m11 = a11 - lmin, m22 = a22 - lmin;
        // rows of (A - lmin I): r0=(m00,a01,a02) r1=(a01,m11,a12) r2=(a02,a12,m22)
        double c1x = a01 * a12 - a02 * m11, c1y = a02 * a01 - m00 * a12, c1z = m00 * m11 - a01 * a01;
        double c2x = a01 * m22 - a02 * a12, c2y = a02 * a02 - m00 * m22, c2z = m00 * a12 - a01 * a02;
        double c3x = m11 * m22 - a12 * a12, c3y = a12 * a02 - a01 * m22, c3z = a01 * a12 - m11 * a02;
        double n1 = c1x * c1x + c1y * c1y + c1z * c1z;
        double n2 = c2x * c2x + c2y * c2y + c2z * c2z;
        double n3 = c3x * c3x + c3y * c3y + c3z * c3z;
        double bx = c1x, by = c1y, bz = c1z, bn = n1;
        if (n2 > bn) { bx = c2x; by = c2y; bz = c2z; bn = n2; }
        if (n3 > bn) { bx = c3x; by = c3y; bz = c3z; bn = n3; }
        if (bn > 1e-100) {
            double si = 1.0 / sqrt(bn);
            vx = bx * si; vy = by * si; vz = bz * si;
        } else {
            // doubly-degenerate smallest eigenvalue: any vector orthogonal to
            // the dominant row of (A - lmin I)
            double r0n = m00 * m00 + a01 * a01 + a02 * a02;
            double r1n = a01 * a01 + m11 * m11 + a12 * a12;
            double r2n = a02 * a02 + a12 * a12 + m22 * m22;
            double wx = m00, wy = a01, wz = a02, wn = r0n;
            if (r1n > wn) { wx = a01; wy = m11; wz = a12; wn = r1n; }
            if (r2n > wn) { wx = a02; wy = a12; wz = m22; wn = r2n; }
            if (wn > 1e-100) {
                double fx = fabs(wx), fy = fabs(wy), fz = fabs(wz);
                double ex = 0.0, ey = 0.0, ez = 0.0;
                if (fx <= fy && fx <= fz) ex = 1.0;
                else if (fy <= fz)        ey = 1.0;
                else                      ez = 1.0;
                double ux = wy * ez - wz * ey;
                double uy = wz * ex - wx * ez;
                double uz = wx * ey - wy * ex;
                double un = ux * ux + uy * uy + uz * uz;
                double si = 1.0 / sqrt(un);
                vx = ux * si; vy = uy * si; vz = uz * si;
            }
        }
    }

    const int gi = b * NPTS + p;
    g_nrm[cloud][0][gi] = (float)vx;
    g_nrm[cloud][1][gi] = (float)vy;
    g_nrm[cloud][2][gi] = (float)vz;
}

__global__ void loss_kernel(float* __restrict__ out) {
    __shared__ float red[TPB];
    float acc = 0.0f;
    for (int i = threadIdx.x; i < NB * NPTS; i += TPB) {
        float px = g_nrm[0][0][i], py = g_nrm[0][1][i], pz = g_nrm[0][2][i];
        float gx = g_nrm[1][0][i], gy = g_nrm[1][1][i], gz = g_nrm[1][2][i];
        float dot = px * gx + py * gy + pz * gz;
        float dn  = sqrtf(px * px + py * py + pz * pz)
                  * sqrtf(gx * gx + gy * gy + gz * gz);
        float cs = dot / fmaxf(dn, 1e-8f);
        acc += 1.0f - fabsf(cs);
    }
    red[threadIdx.x] = acc;
    __syncthreads();
    for (int s = TPB / 2; s > 0; s >>= 1) {
        if (threadIdx.x < s) red[threadIdx.x] += red[threadIdx.x + s];
        __syncthreads();
    }
    if (threadIdx.x == 0) out[0] = red[0] * (1.0f / (float)(NB * NPTS));
}

extern "C" void kernel_launch(void* const* d_in, const int* in_sizes, int n_in,
                              void* d_out, int out_size) {
    (void)in_sizes; (void)n_in; (void)out_size;
    const float* pred = (const float*)d_in[0];
    const float* gt   = (const float*)d_in[1];
    float* out = (float*)d_out;

    static bool attr_done = false;
    const int smem = NPTS * (int)sizeof(float4);   // 64 KB
    if (!attr_done) {
        cudaFuncSetAttribute(normals_kernel,
                             cudaFuncAttributeMaxDynamicSharedMemorySize, smem);
        attr_done = true;
    }

    dim3 grid(NPTS / TPB, NB, 2);
    normals_kernel<<<grid, TPB, smem>>>(pred, gt);
    loss_kernel<<<1, TPB>>>(out);
}

// round 6
// speedup vs baseline: 1.2598x; 1.2598x over previous
#include <cuda_runtime.h>
#include <math.h>

#define NPTS 4096
#define NB   8
#define KNN  10
#define TPB  256
#define LOSS_BLOCKS 128   // 128 * 256 = 32768 = NB * NPTS  (round-5 bug: was 96)

// scratch normals: [cloud][component][b*NPTS + n]
__device__ float g_nrm[2][3][NB * NPTS];

// monotone float -> ordered uint transform (preserves <)
__device__ __forceinline__ unsigned fkey(float f) {
    unsigned b = __float_as_uint(f);
    unsigned m = (unsigned)((int)b >> 31) | 0x80000000u;
    return b ^ m;
}

// branch-free sorted-insert ripple of packed key k into ascending a[0..9]
__device__ __forceinline__ void ripple(unsigned (&a)[KNN], unsigned k) {
#pragma unroll
    for (int r = 0; r < KNN; ++r) {
        unsigned lo = min(a[r], k);
        k = max(a[r], k);
        a[r] = lo;
    }
}

__global__ void __launch_bounds__(TPB, 2)
normals_kernel(const float* __restrict__ pred, const float* __restrict__ gt,
               float* __restrict__ out) {
    extern __shared__ float4 s[];   // 4096 x (x, y, z, |c|^2) = 64 KB

    // zero the loss accumulator once per replay (stream-ordered before loss_kernel)
    if (blockIdx.x == 0 && blockIdx.y == 0 && blockIdx.z == 0 && threadIdx.x == 0)
        out[0] = 0.0f;

    const int cloud = blockIdx.z;
    const int b     = blockIdx.y;
    const float* __restrict__ base =
        ((cloud == 0) ? pred : gt) + (size_t)b * 3 * NPTS;

    // cooperative load of the whole cloud-batch into shared
    for (int t = threadIdx.x; t < NPTS; t += TPB) {
        float x = base[t];
        float y = base[NPTS + t];
        float z = base[2 * NPTS + t];
        s[t] = make_float4(x, y, z, fmaf(x, x, fmaf(y, y, z * z)));
    }
    __syncthreads();

    const int p = blockIdx.x * TPB + threadIdx.x;   // query point
    const float4 q = s[p];
    const float ax = -2.0f * q.x, ay = -2.0f * q.y, az = -2.0f * q.z;
    const float qw = q.w;   // |q|^2: added back at key time for resolution

    // register-resident ascending top-10 of packed keys (dist[31:12] | idx[11:0])
    unsigned a[KNN];
#pragma unroll
    for (int r = 0; r < KNN; ++r) a[r] = 0xFFFFFFFFu;

    // distance proxy: |c|^2 - 2 q.c  (true d2 = proxy + |q|^2, restored at pack time)
    for (int j = 0; j < NPTS; j += 4) {
        float4 c0 = s[j + 0];
        float4 c1 = s[j + 1];
        float4 c2 = s[j + 2];
        float4 c3 = s[j + 3];
        float d0 = fmaf(ax, c0.x, fmaf(ay, c0.y, fmaf(az, c0.z, c0.w)));
        float d1 = fmaf(ax, c1.x, fmaf(ay, c1.y, fmaf(az, c1.z, c1.w)));
        float d2 = fmaf(ax, c2.x, fmaf(ay, c2.y, fmaf(az, c2.z, c2.w)));
        float d3 = fmaf(ax, c3.x, fmaf(ay, c3.y, fmaf(az, c3.z, c3.w)));
        float m = fminf(fminf(d0, d1), fminf(d2, d3));
        if (fkey(m + qw) < a[KNN - 1]) {     // warp-level rare-ish path
            ripple(a, (fkey(d0 + qw) & 0xFFFFF000u) | (unsigned)(j + 0));
            ripple(a, (fkey(d1 + qw) & 0xFFFFF000u) | (unsigned)(j + 1));
            ripple(a, (fkey(d2 + qw) & 0xFFFFF000u) | (unsigned)(j + 2));
            ripple(a, (fkey(d3 + qw) & 0xFFFFF000u) | (unsigned)(j + 3));
        }
    }

    // ---- local covariance of the 10 neighbors (centered on q for stability) --
    float mx = 0.f, my = 0.f, mz = 0.f;
#pragma unroll
    for (int r = 0; r < KNN; ++r) {
        float4 c = s[a[r] & 0xFFFu];
        mx += c.x - q.x; my += c.y - q.y; mz += c.z - q.z;
    }
    const float invk = 1.0f / (float)KNN;
    mx *= invk; my *= invk; mz *= invk;

    float cxx = 0.f, cxy = 0.f, cxz = 0.f, cyy = 0.f, cyz = 0.f, czz = 0.f;
#pragma unroll
    for (int r = 0; r < KNN; ++r) {
        float4 c = s[a[r] & 0xFFFu];
        float dx = (c.x - q.x) - mx;
        float dy = (c.y - q.y) - my;
        float dz = (c.z - q.z) - mz;
        cxx = fmaf(dx, dx, cxx); cxy = fmaf(dx, dy, cxy); cxz = fmaf(dx, dz, cxz);
        cyy = fmaf(dy, dy, cyy); cyz = fmaf(dy, dz, cyz); czz = fmaf(dz, dz, czz);
    }

    // ---- analytic smallest-eigenvector of 3x3 symmetric (double precision) ---
    double a00 = (double)cxx * invk, a01 = (double)cxy * invk, a02 = (double)cxz * invk;
    double a11 = (double)cyy * invk, a12 = (double)cyz * invk, a22 = (double)czz * invk;

    double vx = 1.0, vy = 0.0, vz = 0.0;

    double tr3 = (a00 + a11 + a22) * (1.0 / 3.0);
    double b00 = a00 - tr3, b11 = a11 - tr3, b22 = a22 - tr3;
    double p2 = b00 * b00 + b11 * b11 + b22 * b22
              + 2.0 * (a01 * a01 + a02 * a02 + a12 * a12);
    if (p2 > 0.0) {
        double pp = sqrt(p2 * (1.0 / 6.0));
        double ip = 1.0 / pp;
        double db00 = b00 * ip, db11 = b11 * ip, db22 = b22 * ip;
        double da01 = a01 * ip, da02 = a02 * ip, da12 = a12 * ip;
        double halfdet = 0.5 * (db00 * (db11 * db22 - da12 * da12)
                              - da01 * (da01 * db22 - da12 * da02)
                              + da02 * (da01 * da12 - db11 * da02));
        halfdet = fmin(fmax(halfdet, -1.0), 1.0);
        double ang  = acos(halfdet) * (1.0 / 3.0);
        double lmin = tr3 + 2.0 * pp * cos(ang + 2.0943951023931953);  // +2pi/3

        double m00 = a00 - lmin, m11 = a11 - lmin, m22 = a22 - lmin;
        double c1x = a01 * a12 - a02 * m11, c1y = a02 * a01 - m00 * a12, c1z = m00 * m11 - a01 * a01;
        double c2x = a01 * m22 - a02 * a12, c2y = a02 * a02 - m00 * m22, c2z = m00 * a12 - a01 * a02;
        double c3x = m11 * m22 - a12 * a12, c3y = a12 * a02 - a01 * m22, c3z = a01 * a12 - m11 * a02;
        double n1 = c1x * c1x + c1y * c1y + c1z * c1z;
        double n2 = c2x * c2x + c2y * c2y + c2z * c2z;
        double n3 = c3x * c3x + c3y * c3y + c3z * c3z;
        double bx = c1x, by = c1y, bz = c1z, bn = n1;
        if (n2 > bn) { bx = c2x; by = c2y; bz = c2z; bn = n2; }
        if (n3 > bn) { bx = c3x; by = c3y; bz = c3z; bn = n3; }
        if (bn > 1e-100) {
            double si = 1.0 / sqrt(bn);
            vx = bx * si; vy = by * si; vz = bz * si;
        } else {
            // doubly-degenerate smallest eigenvalue: any vector orthogonal to
            // the dominant row of (A - lmin I)
            double r0n = m00 * m00 + a01 * a01 + a02 * a02;
            double r1n = a01 * a01 + m11 * m11 + a12 * a12;
            double r2n = a02 * a02 + a12 * a12 + m22 * m22;
            double wx = m00, wy = a01, wz = a02, wn = r0n;
            if (r1n > wn) { wx = a01; wy = m11; wz = a12; wn = r1n; }
            if (r2n > wn) { wx = a02; wy = a12; wz = m22; wn = r2n; }
            if (wn > 1e-100) {
                double fx = fabs(wx), fy = fabs(wy), fz = fabs(wz);
                double ex = 0.0, ey = 0.0, ez = 0.0;
                if (fx <= fy && fx <= fz) ex = 1.0;
                else if (fy <= fz)        ey = 1.0;
                else                      ez = 1.0;
                double ux = wy * ez - wz * ey;
                double uy = wz * ex - wx * ez;
                double uz = wx * ey - wy * ex;
                double un = ux * ux + uy * uy + uz * uz;
                double si = 1.0 / sqrt(un);
                vx = ux * si; vy = uy * si; vz = uz * si;
            }
        }
    }

    const int gi = b * NPTS + p;
    g_nrm[cloud][0][gi] = (float)vx;
    g_nrm[cloud][1][gi] = (float)vy;
    g_nrm[cloud][2][gi] = (float)vz;
}

__global__ void loss_kernel(float* __restrict__ out) {
    __shared__ float wsum[TPB / 32];
    const int i = blockIdx.x * TPB + threadIdx.x;   // LOSS_BLOCKS*TPB == NB*NPTS
    float px = g_nrm[0][0][i], py = g_nrm[0][1][i], pz = g_nrm[0][2][i];
    float gx = g_nrm[1][0][i], gy = g_nrm[1][1][i], gz = g_nrm[1][2][i];
    float dot = px * gx + py * gy + pz * gz;
    float dn  = sqrtf(px * px + py * py + pz * pz)
              * sqrtf(gx * gx + gy * gy + gz * gz);
    float cs  = dot / fmaxf(dn, 1e-8f);
    float v   = 1.0f - fabsf(cs);

#pragma unroll
    for (int o = 16; o > 0; o >>= 1)
        v += __shfl_down_sync(0xFFFFFFFFu, v, o);
    if ((threadIdx.x & 31) == 0) wsum[threadIdx.x >> 5] = v;
    __syncthreads();
    if (threadIdx.x < TPB / 32) {
        float b = wsum[threadIdx.x];
#pragma unroll
        for (int o = TPB / 64; o > 0; o >>= 1)
            b += __shfl_down_sync(0xFFu, b, o);
        if (threadIdx.x == 0)
            atomicAdd(out, b * (1.0f / (float)(NB * NPTS)));
    }
}

extern "C" void kernel_launch(void* const* d_in, const int* in_sizes, int n_in,
                              void* d_out, int out_size) {
    (void)in_sizes; (void)n_in; (void)out_size;
    const float* pred = (const float*)d_in[0];
    const float* gt   = (const float*)d_in[1];
    float* out = (float*)d_out;

    static bool attr_done = false;
    const int smem = NPTS * (int)sizeof(float4);   // 64 KB
    if (!attr_done) {
        cudaFuncSetAttribute(normals_kernel,
                             cudaFuncAttributeMaxDynamicSharedMemorySize, smem);
        attr_done = true;
    }

    dim3 grid(NPTS / TPB, NB, 2);
    normals_kernel<<<grid, TPB, smem>>>(pred, gt, out);
    loss_kernel<<<LOSS_BLOCKS, TPB>>>(out);
}

// round 8
// speedup vs baseline: 1.5778x; 1.2524x over previous
#include <cuda_runtime.h>
#include <math.h>

#define NPTS 4096
#define NB   8
#define KNN  10
#define TPB  256
#define LOSS_BLOCKS 128   // 128 * 256 = 32768 = NB * NPTS

// scratch normals: [cloud][component][b*NPTS + n]
__device__ float g_nrm[2][3][NB * NPTS];

// monotone float -> ordered uint transform (preserves <), handles negatives
__device__ __forceinline__ unsigned fkey(float f) {
    unsigned b = __float_as_uint(f);
    unsigned m = (unsigned)((int)b >> 31) | 0x80000000u;
    return b ^ m;
}

// inverse for positive-distance keys (MSB set): clear MSB
__device__ __forceinline__ float ikey_pos(unsigned k) {
    return __uint_as_float(k ^ 0x80000000u);
}

// branch-free sorted-insert ripple of packed key k into ascending a[0..9]
__device__ __forceinline__ void ripple(unsigned (&a)[KNN], unsigned k) {
#pragma unroll
    for (int r = 0; r < KNN; ++r) {
        unsigned lo = min(a[r], k);
        k = max(a[r], k);
        a[r] = lo;
    }
}

__global__ void __launch_bounds__(TPB, 2)
normals_kernel(const float* __restrict__ pred, const float* __restrict__ gt,
               float* __restrict__ out) {
    extern __shared__ float4 s[];   // 4096 x (x, y, z, |c|^2) = 64 KB

    // zero the loss accumulator once per replay (stream-ordered before loss_kernel)
    if (blockIdx.x == 0 && blockIdx.y == 0 && blockIdx.z == 0 && threadIdx.x == 0)
        out[0] = 0.0f;

    const int cloud = blockIdx.z;
    const int b     = blockIdx.y;
    const float* __restrict__ base =
        ((cloud == 0) ? pred : gt) + (size_t)b * 3 * NPTS;

    // cooperative load of the whole cloud-batch into shared
    for (int t = threadIdx.x; t < NPTS; t += TPB) {
        float x = base[t];
        float y = base[NPTS + t];
        float z = base[2 * NPTS + t];
        s[t] = make_float4(x, y, z, fmaf(x, x, fmaf(y, y, z * z)));
    }
    __syncthreads();

    const int p = blockIdx.x * TPB + threadIdx.x;   // query point
    const float4 q = s[p];
    const float ax = -2.0f * q.x, ay = -2.0f * q.y, az = -2.0f * q.z;
    const float qw = q.w;

    // register-resident ascending top-10 of packed keys (dist[31:12] | idx[11:0])
    // init = fkey(FLT_MAX) & ~0xFFF, so ikey_pos(a[9]|0xFFF) is finite (FLT_MAX)
    unsigned a[KNN];
#pragma unroll
    for (int r = 0; r < KNN; ++r) a[r] = 0xFF7FF000u;

    // live float threshold: upper bound of the 10th-best distance
    float thr = 3.4e38f;

    // true d2 = |c|^2 + |q|^2 - 2 q.c, folded into one fma chain
    for (int j = 0; j < NPTS; j += 4) {
        float4 c0 = s[j + 0];
        float4 c1 = s[j + 1];
        float4 c2 = s[j + 2];
        float4 c3 = s[j + 3];
        float d0 = fmaf(ax, c0.x, fmaf(ay, c0.y, fmaf(az, c0.z, c0.w + qw)));
        float d1 = fmaf(ax, c1.x, fmaf(ay, c1.y, fmaf(az, c1.z, c1.w + qw)));
        float d2 = fmaf(ax, c2.x, fmaf(ay, c2.y, fmaf(az, c2.z, c2.w + qw)));
        float d3 = fmaf(ax, c3.x, fmaf(ay, c3.y, fmaf(az, c3.z, c3.w + qw)));
        float m = fminf(fminf(d0, d1), fminf(d2, d3));
        if (m < thr) {
            if (d0 < thr) {
                ripple(a, (fkey(d0) & 0xFFFFF000u) | (unsigned)(j + 0));
                thr = ikey_pos(a[KNN - 1] | 0xFFFu);
            }
            if (d1 < thr) {
                ripple(a, (fkey(d1) & 0xFFFFF000u) | (unsigned)(j + 1));
                thr = ikey_pos(a[KNN - 1] | 0xFFFu);
            }
            if (d2 < thr) {
                ripple(a, (fkey(d2) & 0xFFFFF000u) | (unsigned)(j + 2));
                thr = ikey_pos(a[KNN - 1] | 0xFFFu);
            }
            if (d3 < thr) {
                ripple(a, (fkey(d3) & 0xFFFFF000u) | (unsigned)(j + 3));
                thr = ikey_pos(a[KNN - 1] | 0xFFFu);
            }
        }
    }

    // ---- local covariance of the 10 neighbors (centered on q for stability) --
    float mx = 0.f, my = 0.f, mz = 0.f;
#pragma unroll
    for (int r = 0; r < KNN; ++r) {
        float4 c = s[a[r] & 0xFFFu];
        mx += c.x - q.x; my += c.y - q.y; mz += c.z - q.z;
    }
    const float invk = 1.0f / (float)KNN;
    mx *= invk; my *= invk; mz *= invk;

    float cxx = 0.f, cxy = 0.f, cxz = 0.f, cyy = 0.f, cyz = 0.f, czz = 0.f;
#pragma unroll
    for (int r = 0; r < KNN; ++r) {
        float4 c = s[a[r] & 0xFFFu];
        float dx = (c.x - q.x) - mx;
        float dy = (c.y - q.y) - my;
        float dz = (c.z - q.z) - mz;
        cxx = fmaf(dx, dx, cxx); cxy = fmaf(dx, dy, cxy); cxz = fmaf(dx, dz, cxz);
        cyy = fmaf(dy, dy, cyy); cyz = fmaf(dy, dz, cyz); czz = fmaf(dz, dz, czz);
    }

    // ---- analytic smallest-eigenvector of 3x3 symmetric (double precision) ---
    double a00 = (double)cxx * invk, a01 = (double)cxy * invk, a02 = (double)cxz * invk;
    double a11 = (double)cyy * invk, a12 = (double)cyz * invk, a22 = (double)czz * invk;

    double vx = 1.0, vy = 0.0, vz = 0.0;

    double tr3 = (a00 + a11 + a22) * (1.0 / 3.0);
    double b00 = a00 - tr3, b11 = a11 - tr3, b22 = a22 - tr3;
    double p2 = b00 * b00 + b11 * b11 + b22 * b22
              + 2.0 * (a01 * a01 + a02 * a02 + a12 * a12);
    if (p2 > 0.0) {
        double pp = sqrt(p2 * (1.0 / 6.0));
        double ip = 1.0 / pp;
        double db00 = b00 * ip, db11 = b11 * ip, db22 = b22 * ip;
        double da01 = a01 * ip, da02 = a02 * ip, da12 = a12 * ip;
        double halfdet = 0.5 * (db00 * (db11 * db22 - da12 * da12)
                              - da01 * (da01 * db22 - da12 * da02)
                              + da02 * (da01 * da12 - db11 * da02));
        halfdet = fmin(fmax(halfdet, -1.0), 1.0);
        double ang  = acos(halfdet) * (1.0 / 3.0);
        double lmin = tr3 + 2.0 * pp * cos(ang + 2.0943951023931953);  // +2pi/3

        double m00 = a00 - lmin, m11 = a11 - lmin, m22 = a22 - lmin;
        double c1x = a01 * a12 - a02 * m11, c1y = a02 * a01 - m00 * a12, c1z = m00 * m11 - a01 * a01;
        double c2x = a01 * m22 - a02 * a12, c2y = a02 * a02 - m00 * m22, c2z = m00 * a12 - a01 * a02;
        double c3x = m11 * m22 - a12 * a12, c3y = a12 * a02 - a01 * m22, c3z = a01 * a12 - m11 * a02;
        double n1 = c1x * c1x + c1y * c1y + c1z * c1z;
        double n2 = c2x * c2x + c2y * c2y + c2z * c2z;
        double n3 = c3x * c3x + c3y * c3y + c3z * c3z;
        double bx = c1x, by = c1y, bz = c1z, bn = n1;
        if (n2 > bn) { bx = c2x; by = c2y; bz = c2z; bn = n2; }
        if (n3 > bn) { bx = c3x; by = c3y; bz = c3z; bn = n3; }
        if (bn > 1e-100) {
            double si = 1.0 / sqrt(bn);
            vx = bx * si; vy = by * si; vz = bz * si;
        } else {
            // doubly-degenerate smallest eigenvalue: any vector orthogonal to
            // the dominant row of (A - lmin I)
            double r0n = m00 * m00 + a01 * a01 + a02 * a02;
            double r1n = a01 * a01 + m11 * m11 + a12 * a12;
            double r2n = a02 * a02 + a12 * a12 + m22 * m22;
            double wx = m00, wy = a01, wz = a02, wn = r0n;
            if (r1n > wn) { wx = a01; wy = m11; wz = a12; wn = r1n; }
            if (r2n > wn) { wx = a02; wy = a12; wz = m22; wn = r2n; }
            if (wn > 1e-100) {
                double fx = fabs(wx), fy = fabs(wy), fz = fabs(wz);
                double ex = 0.0, ey = 0.0, ez = 0.0;
                if (fx <= fy && fx <= fz) ex = 1.0;
                else if (fy <= fz)        ey = 1.0;
                else                      ez = 1.0;
                double ux = wy * ez - wz * ey;
                double uy = wz * ex - wx * ez;
                double uz = wx * ey - wy * ex;
                double un = ux * ux + uy * uy + uz * uz;
                double si = 1.0 / sqrt(un);
                vx = ux * si; vy = uy * si; vz = uz * si;
            }
        }
    }

    const int gi = b * NPTS + p;
    g_nrm[cloud][0][gi] = (float)vx;
    g_nrm[cloud][1][gi] = (float)vy;
    g_nrm[cloud][2][gi] = (float)vz;
}

__global__ void loss_kernel(float* __restrict__ out) {
    __shared__ float wsum[TPB / 32];
    const int i = blockIdx.x * TPB + threadIdx.x;   // LOSS_BLOCKS*TPB == NB*NPTS
    float px = g_nrm[0][0][i], py = g_nrm[0][1][i], pz = g_nrm[0][2][i];
    float gx = g_nrm[1][0][i], gy = g_nrm[1][1][i], gz = g_nrm[1][2][i];
    float dot = px * gx + py * gy + pz * gz;
    float dn  = sqrtf(px * px + py * py + pz * pz)
              * sqrtf(gx * gx + gy * gy + gz * gz);
    float cs  = dot / fmaxf(dn, 1e-8f);
    float v   = 1.0f - fabsf(cs);

#pragma unroll
    for (int o = 16; o > 0; o >>= 1)
        v += __shfl_down_sync(0xFFFFFFFFu, v, o);
    if ((threadIdx.x & 31) == 0) wsum[threadIdx.x >> 5] = v;
    __syncthreads();
    if (threadIdx.x < TPB / 32) {
        float b = wsum[threadIdx.x];
#pragma unroll
        for (int o = TPB / 64; o > 0; o >>= 1)
            b += __shfl_down_sync(0xFFu, b, o);
        if (threadIdx.x == 0)
            atomicAdd(out, b * (1.0f / (float)(NB * NPTS)));
    }
}

extern "C" void kernel_launch(void* const* d_in, const int* in_sizes, int n_in,
                              void* d_out, int out_size) {
    (void)in_sizes; (void)n_in; (void)out_size;
    const float* pred = (const float*)d_in[0];
    const float* gt   = (const float*)d_in[1];
    float* out = (float*)d_out;

    static bool attr_done = false;
    const int smem = NPTS * (int)sizeof(float4);   // 64 KB
    if (!attr_done) {
        cudaFuncSetAttribute(normals_kernel,
                             cudaFuncAttributeMaxDynamicSharedMemorySize, smem);
        attr_done = true;
    }

    dim3 grid(NPTS / TPB, NB, 2);
    normals_kernel<<<grid, TPB, smem>>>(pred, gt, out);
    loss_kernel<<<LOSS_BLOCKS, TPB>>>(out);
}